// round 1
// baseline (speedup 1.0000x reference)
#include <cuda_runtime.h>
#include <cuda_bf16.h>

// Problem sizes (fixed by the reference)
#define BATCH    4096
#define FNUM     1024
#define RC       19
#define EDIM     1024
#define ESPLIT   8            // e-dimension split for the W kernel
#define FPT      4            // f rows per thread in main kernel (1024 / 256)
#define NBLOCKS  592          // persistent grid (148 SMs * 4)

// Scratch for W[f,r] = sum_e U[f,e] * R[r,e]  (no device allocs allowed)
__device__ float g_W[FNUM * RC];

// ---------------------------------------------------------------------------
// Kernel 0: zero the W scratch (needed because kernel 1 accumulates atomically)
// ---------------------------------------------------------------------------
__global__ void zero_W_kernel() {
    int i = blockIdx.x * blockDim.x + threadIdx.x;
    if (i < FNUM * RC) g_W[i] = 0.0f;
}

// ---------------------------------------------------------------------------
// Kernel 1: W[f,r] = sum_e U[f,e] * R[r,e]
// One thread per (f, r, e-slice). Within a warp, consecutive flat outputs
// share f (19 outputs per f) -> U loads are ~2-line broadcasts per warp.
// R (76 KB) stays hot in L1/L2. Partial sums combined with atomicAdd.
// ---------------------------------------------------------------------------
__global__ void compute_W_kernel(const float* __restrict__ U,
                                 const float* __restrict__ R) {
    const int idx = blockIdx.x * blockDim.x + threadIdx.x;   // [0, FNUM*RC)
    if (idx >= FNUM * RC) return;
    const int slice = blockIdx.y;                            // [0, ESPLIT)
    const int f = idx / RC;
    const int r = idx % RC;
    const int e0 = slice * (EDIM / ESPLIT);

    const float* __restrict__ u  = U + (size_t)f * EDIM + e0;
    const float* __restrict__ rr = R + (size_t)r * EDIM + e0;

    float acc = 0.0f;
#pragma unroll 8
    for (int e = 0; e < EDIM / ESPLIT; ++e)
        acc = fmaf(u[e], rr[e], acc);

    atomicAdd(&g_W[idx], acc);
}

// ---------------------------------------------------------------------------
// Kernel 2: scores[b,r] = sum_f conv[b,f,r] * W[f,r]
// Persistent blocks. Each thread owns f = tid, tid+256, tid+512, tid+768 and
// caches W[f,0:19] in 76 registers for the whole batch loop. conv[b] is
// streamed from DRAM (each 128B line touched once per block via the L1-held
// per-warp window). 19 register accumulators; shuffle + smem reduction.
// ---------------------------------------------------------------------------
__global__ __launch_bounds__(256)
void score_kernel(const float* __restrict__ conv,
                  float* __restrict__ out) {
    const int tid  = threadIdx.x;
    const int lane = tid & 31;
    const int warp = tid >> 5;

    // Preload this thread's W rows into registers (read from L2, once).
    float w[FPT][RC];
#pragma unroll
    for (int j = 0; j < FPT; ++j) {
        const int f = tid + j * 256;
        const float* __restrict__ wf = &g_W[f * RC];
#pragma unroll
        for (int r = 0; r < RC; ++r) w[j][r] = wf[r];
    }

    __shared__ float red[8][RC];

    for (int b = blockIdx.x; b < BATCH; b += gridDim.x) {
        const float* __restrict__ cb = conv + (size_t)b * (FNUM * RC);

        float acc[RC];
#pragma unroll
        for (int r = 0; r < RC; ++r) acc[r] = 0.0f;

#pragma unroll
        for (int j = 0; j < FPT; ++j) {
            const int f = tid + j * 256;
            const float* __restrict__ cf = cb + (size_t)f * RC;
#pragma unroll
            for (int r = 0; r < RC; ++r)
                acc[r] = fmaf(cf[r], w[j][r], acc[r]);
        }

        // Warp-level tree reduction of each of the 19 accumulators.
#pragma unroll
        for (int r = 0; r < RC; ++r) {
            float v = acc[r];
            v += __shfl_xor_sync(0xffffffffu, v, 16);
            v += __shfl_xor_sync(0xffffffffu, v, 8);
            v += __shfl_xor_sync(0xffffffffu, v, 4);
            v += __shfl_xor_sync(0xffffffffu, v, 2);
            v += __shfl_xor_sync(0xffffffffu, v, 1);
            if (lane == 0) red[warp][r] = v;
        }
        __syncthreads();

        if (tid < RC) {
            float s = 0.0f;
#pragma unroll
            for (int k = 0; k < 8; ++k) s += red[k][tid];
            out[(size_t)b * RC + tid] = s;
        }
        __syncthreads();   // protect red[] before next batch iteration
    }
}

// ---------------------------------------------------------------------------
// Launch: inputs are (conv_output [4096,1024,19], R_output [19,1024],
//                     U [1024,1024]); output float [4096,19].
// Three kernel launches, no syncs/allocs -> graph-capturable.
// ---------------------------------------------------------------------------
extern "C" void kernel_launch(void* const* d_in, const int* in_sizes, int n_in,
                              void* d_out, int out_size) {
    const float* conv = (const float*)d_in[0];
    const float* R    = (const float*)d_in[1];
    const float* U    = (const float*)d_in[2];
    float* out        = (float*)d_out;

    zero_W_kernel<<<(FNUM * RC + 255) / 256, 256>>>();

    dim3 grid1((FNUM * RC + 255) / 256, ESPLIT);
    compute_W_kernel<<<grid1, 256>>>(U, R);

    score_kernel<<<NBLOCKS, 256>>>(conv, out);
}

// round 2
// speedup vs baseline: 1.3990x; 1.3990x over previous
#include <cuda_runtime.h>
#include <cuda_bf16.h>
#include <cstdint>

#define BATCH     4096
#define FNUM      1024
#define RC        19
#define EDIM      1024
#define ROW_FLOATS (FNUM * RC)        // 19456
#define ROW_BYTES  (ROW_FLOATS * 4)   // 77824 (16B-multiple)
#define THREADS    512
#define FPT        2                  // 1024 f-rows / 512 threads
#define GRID       148                // persistent, 1 block/SM (smem-forced)

// W[f,r] = sum_e U[f,e] * R[r,e]
__device__ float g_W[ROW_FLOATS];

// ---------------------------------------------------------------------------
// Kernel 1: W = U @ R^T, no atomics. One thread per (f,r); float4 dot of 1024.
// 19 consecutive threads share the same U row (L1 broadcast); the 19 R rows
// (76 KB) stay L1/L2 resident.
// ---------------------------------------------------------------------------
__global__ void compute_W_kernel(const float* __restrict__ U,
                                 const float* __restrict__ R) {
    int idx = blockIdx.x * blockDim.x + threadIdx.x;
    if (idx >= ROW_FLOATS) return;
    int f = idx / RC, r = idx % RC;
    const float4* __restrict__ u  = (const float4*)(U + (size_t)f * EDIM);
    const float4* __restrict__ rr = (const float4*)(R + (size_t)r * EDIM);
    float a0 = 0.f, a1 = 0.f, a2 = 0.f, a3 = 0.f;
#pragma unroll 4
    for (int e = 0; e < EDIM / 4; ++e) {
        float4 uv = u[e], rv = rr[e];
        a0 = fmaf(uv.x, rv.x, a0);
        a1 = fmaf(uv.y, rv.y, a1);
        a2 = fmaf(uv.z, rv.z, a2);
        a3 = fmaf(uv.w, rv.w, a3);
    }
    g_W[idx] = (a0 + a1) + (a2 + a3);
}

// ---------------------------------------------------------------------------
// PTX helpers (self-contained)
// ---------------------------------------------------------------------------
__device__ __forceinline__ uint32_t smem_u32(const void* p) {
    uint32_t a;
    asm("{ .reg .u64 t; cvta.to.shared.u64 t, %1; cvt.u32.u64 %0, t; }"
        : "=r"(a) : "l"(p));
    return a;
}

__device__ __forceinline__ void mbar_init(uint32_t mbar, uint32_t count) {
    asm volatile("mbarrier.init.shared.b64 [%0], %1;" :: "r"(mbar), "r"(count) : "memory");
}

__device__ __forceinline__ void mbar_expect_tx(uint32_t mbar, uint32_t bytes) {
    asm volatile("mbarrier.arrive.expect_tx.shared.b64 _, [%0], %1;"
                 :: "r"(mbar), "r"(bytes) : "memory");
}

__device__ __forceinline__ void bulk_load(uint32_t dst_smem, const void* src_gmem,
                                          uint32_t bytes, uint32_t mbar) {
    asm volatile(
        "cp.async.bulk.shared::cta.global.mbarrier::complete_tx::bytes [%0], [%1], %2, [%3];"
        :: "r"(dst_smem), "l"(src_gmem), "r"(bytes), "r"(mbar) : "memory");
}

__device__ __forceinline__ void mbar_wait(uint32_t mbar, uint32_t parity) {
    uint32_t done;
    asm volatile(
        "{\n\t"
        ".reg .pred p;\n\t"
        "mbarrier.try_wait.parity.acquire.cta.shared::cta.b64 p, [%1], %2;\n\t"
        "selp.b32 %0, 1, 0, p;\n\t"
        "}"
        : "=r"(done) : "r"(mbar), "r"(parity) : "memory");
    if (!done) {
        asm volatile(
            "{\n\t"
            ".reg .pred P1;\n\t"
            "WAIT_LOOP_%=:\n\t"
            "mbarrier.try_wait.parity.acquire.cta.shared::cta.b64 P1, [%0], %1, 0x989680;\n\t"
            "@P1 bra.uni WAIT_DONE_%=;\n\t"
            "bra.uni WAIT_LOOP_%=;\n\t"
            "WAIT_DONE_%=:\n\t"
            "}"
            :: "r"(mbar), "r"(parity) : "memory");
    }
}

// ---------------------------------------------------------------------------
// Kernel 2: scores[b,r] = sum_f conv[b,f,r] * W[f,r]
// Persistent 148 blocks, each owns ~27 b's. Per b: cp.async.bulk the full
// 77,824B conv row into smem (double-buffered), then stride-19 LDS
// (conflict-free, gcd(19,32)=1) with W cached in registers.
// ---------------------------------------------------------------------------
extern __shared__ char smem_raw[];

__global__ __launch_bounds__(THREADS, 1)
void score_kernel(const float* __restrict__ conv,
                  float* __restrict__ out) {
    float* buf0 = (float*)smem_raw;
    float* buf1 = buf0 + ROW_FLOATS;
    float* red  = buf1 + ROW_FLOATS;                   // [16][RC]
    uint64_t* mbar = (uint64_t*)(red + (THREADS / 32) * RC);

    const int tid  = threadIdx.x;
    const int lane = tid & 31;
    const int warp = tid >> 5;

    const uint32_t mb0 = smem_u32(&mbar[0]);
    const uint32_t mb1 = smem_u32(&mbar[1]);
    const uint32_t db0 = smem_u32(buf0);
    const uint32_t db1 = smem_u32(buf1);

    // Cache this thread's W rows in registers (constant-indexed).
    float w[FPT][RC];
#pragma unroll
    for (int j = 0; j < FPT; ++j) {
        const float* __restrict__ wf = &g_W[(tid + j * THREADS) * RC];
#pragma unroll
        for (int r = 0; r < RC; ++r) w[j][r] = wf[r];
    }

    const int bx = blockIdx.x;
    const int count = (BATCH - bx + GRID - 1) / GRID;       // b = bx + i*GRID
    const float* __restrict__ base = conv + (size_t)bx * ROW_FLOATS;

    if (tid == 0) {
        mbar_init(mb0, 1);
        mbar_init(mb1, 1);
    }
    __syncthreads();

    if (tid == 0) {
        // Prime the pipeline with up to 2 loads.
        if (count > 0) {
            mbar_expect_tx(mb0, ROW_BYTES);
            bulk_load(db0, base, ROW_BYTES, mb0);
        }
        if (count > 1) {
            mbar_expect_tx(mb1, ROW_BYTES);
            bulk_load(db1, base + (size_t)GRID * ROW_FLOATS, ROW_BYTES, mb1);
        }
    }

    for (int i = 0; i < count; ++i) {
        const int s = i & 1;
        const uint32_t mb = s ? mb1 : mb0;
        const uint32_t db = s ? db1 : db0;
        const float* __restrict__ bufc = s ? buf1 : buf0;
        const int phase = (i >> 1) & 1;

        mbar_wait(mb, phase);

        float acc[RC];
#pragma unroll
        for (int r = 0; r < RC; ++r) acc[r] = 0.f;

#pragma unroll
        for (int j = 0; j < FPT; ++j) {
            const float* __restrict__ cf = bufc + (tid + j * THREADS) * RC;
#pragma unroll
            for (int r = 0; r < RC; ++r)
                acc[r] = fmaf(cf[r], w[j][r], acc[r]);
        }

        // Warp tree reduction of the 19 accumulators.
#pragma unroll
        for (int r = 0; r < RC; ++r) {
            float v = acc[r];
            v += __shfl_xor_sync(0xffffffffu, v, 16);
            v += __shfl_xor_sync(0xffffffffu, v, 8);
            v += __shfl_xor_sync(0xffffffffu, v, 4);
            v += __shfl_xor_sync(0xffffffffu, v, 2);
            v += __shfl_xor_sync(0xffffffffu, v, 1);
            if (lane == 0) red[warp * RC + r] = v;
        }
        __syncthreads();   // all buf reads finished; red fully written

        // Buffer s is now free: issue load for iteration i+2 into it.
        if (tid == 0 && i + 2 < count) {
            mbar_expect_tx(mb, ROW_BYTES);
            bulk_load(db, base + (size_t)(i + 2) * GRID * ROW_FLOATS, ROW_BYTES, mb);
        }

        if (tid < RC) {
            float ssum = 0.f;
#pragma unroll
            for (int k = 0; k < THREADS / 32; ++k) ssum += red[k * RC + tid];
            out[((size_t)bx + (size_t)i * GRID) * RC + tid] = ssum;
        }
        __syncthreads();   // red safe for reuse next iteration
    }
}

// ---------------------------------------------------------------------------
// Launch
// ---------------------------------------------------------------------------
extern "C" void kernel_launch(void* const* d_in, const int* in_sizes, int n_in,
                              void* d_out, int out_size) {
    const float* conv = (const float*)d_in[0];
    const float* R    = (const float*)d_in[1];
    const float* U    = (const float*)d_in[2];
    float* out        = (float*)d_out;

    compute_W_kernel<<<(ROW_FLOATS + 255) / 256, 256>>>(U, R);

    const int smem_bytes = 2 * ROW_BYTES + (THREADS / 32) * RC * 4 + 16;
    cudaFuncSetAttribute(score_kernel,
                         cudaFuncAttributeMaxDynamicSharedMemorySize, smem_bytes);
    score_kernel<<<GRID, THREADS, smem_bytes>>>(conv, out);
}